// round 8
// baseline (speedup 1.0000x reference)
#include <cuda_runtime.h>
#include <cuda_bf16.h>
#include <math.h>
#include <stdint.h>

// ---------------------------------------------------------------------------
// Swin block: B=16, C=384, H=W=56, NH=12, WS=7, SS=3, MLP=1536
// GEMMs: mma.sync tf32, 128x128 CTA / 64x32 warp, 4-stage cp.async pipeline.
// tf32 rounding moved to producers; weights pre-rounded + transposed.
// ---------------------------------------------------------------------------
#define TOK   50176
#define CCH   384
#define HH    56
#define WW2   56
#define NWIN  1024
#define NTOK  49
#define NHEAD 12
#define HDIM  32
#define MLPD  1536

#define STAGES 4
#define GEMM_SMEM (STAGES * 16384)          // 64 KB dynamic

// Scratch
__device__ float g_xbhwc[TOK * CCH];
__device__ float g_xw   [TOK * CCH];        // tf32-rounded
__device__ float g_q    [TOK * CCH];
__device__ float g_k    [TOK * CCH];
__device__ float g_v    [TOK * CCH];
__device__ float g_ao   [TOK * CCH];        // tf32-rounded
__device__ float g_x2   [TOK * CCH];
__device__ float g_xn2  [TOK * CCH];        // tf32-rounded
__device__ float g_h1   [TOK * MLPD];       // tf32-rounded
__device__ float g_y    [TOK * CCH];
// tf32-rounded, transposed weights [N][K]
__device__ float g_wt_qkv [1152 * 384];
__device__ float g_wt_proj[384 * 384];
__device__ float g_wt_fc1 [MLPD * 384];
__device__ float g_wt_fc2 [384 * MLPD];

__device__ __forceinline__ float tf32r(float f) {
    uint32_t u;
    asm("cvt.rna.tf32.f32 %0, %1;" : "=r"(u) : "f"(f));
    return __uint_as_float(u);
}
__device__ __forceinline__ uint32_t smem_u32(const void* p) {
    uint32_t a;
    asm("{ .reg .u64 t; cvta.to.shared.u64 t, %1; cvt.u32.u64 %0, t; }"
        : "=r"(a) : "l"(p));
    return a;
}
#define CP_ASYNC16(dst, src) \
    asm volatile("cp.async.cg.shared.global [%0], [%1], 16;" \
                 :: "r"(dst), "l"(src))
#define CP_COMMIT() asm volatile("cp.async.commit_group;" ::: "memory")

// ---------------------------------------------------------------------------
// K0: weight prep: W[K][N] -> Wt[N][K], tf32-rounded
// ---------------------------------------------------------------------------
__global__ void __launch_bounds__(256) k_wtprep(const float* __restrict__ W,
                                                float* __restrict__ Wt,
                                                int K, int N)
{
    __shared__ float t[32][33];
    const int n0 = blockIdx.x * 32, k0 = blockIdx.y * 32;
    const int lx = threadIdx.x & 31, ly = threadIdx.x >> 5;
#pragma unroll
    for (int i = 0; i < 4; i++)
        t[ly + i * 8][lx] = W[(size_t)(k0 + ly + i * 8) * N + n0 + lx];
    __syncthreads();
#pragma unroll
    for (int i = 0; i < 4; i++)
        Wt[(size_t)(n0 + ly + i * 8) * K + k0 + lx] = tf32r(t[lx][ly + i * 8]);
}

// ---------------------------------------------------------------------------
// tf32 mma.sync GEMM: C = A[M,K] * Bt[N,K]^T.  Both operands pre-tf32-rounded.
// CTA 128x128, 8 warps (2M x 4N), warp 64x32, k-chunk 16, 4-stage cp.async.
// Crosswise smem [stage][kgroup][x][4]: 16B global chunk -> contiguous 16B
// smem chunk; every fragment LDS.32 is one 128B wavefront.
// MODE 0: QKV split  1: proj+winrev+residual  2: fc1+GELU  3: fc2+residual
// ---------------------------------------------------------------------------
template <int MODE>
__global__ void __launch_bounds__(256, 2) k_gemm_mma(
    const float* __restrict__ A, const float* __restrict__ Bt,
    const float* __restrict__ bias, int K, int N, int NC)
{
    extern __shared__ float smem[];
    float* As = smem;                       // [STAGES][4][128][4]
    float* Bs = smem + STAGES * 2048;       // [STAGES][4][128][4]

    const int tid = threadIdx.x;
    const int wid = tid >> 5, lane = tid & 31;
    const int gid = lane >> 2, tig = lane & 3;
    const int wm = wid & 1, wn = wid >> 1;       // 2 x 4 warp grid
    const int m0 = blockIdx.y * 128, n0 = blockIdx.x * 128;

    const uint32_t sA = smem_u32(As), sB = smem_u32(Bs);
    const int c_row = tid >> 2, c_q = tid & 3;   // 64 rows per t-step? no: 128/2

    float acc[4][4][4];
#pragma unroll
    for (int a = 0; a < 4; a++)
#pragma unroll
        for (int b = 0; b < 4; b++)
#pragma unroll
            for (int c = 0; c < 4; c++) acc[a][b][c] = 0.f;

    const float* Abase = A + (size_t)m0 * K;
    const float* Bbase = Bt + (size_t)n0 * K;

    auto issue_stage = [&](int c, int s) {
        const float* Asrc = Abase + c * 16;
        const float* Bsrc = Bbase + c * 16;
#pragma unroll
        for (int t = 0; t < 2; t++) {
            int idx = t * 256 + tid;           // 0..511
            int row = idx >> 2, q = idx & 3;
            CP_ASYNC16(sA + ((s * 4 + q) * 128 + row) * 16,
                       Asrc + (size_t)row * K + q * 4);
            CP_ASYNC16(sB + ((s * 4 + q) * 128 + row) * 16,
                       Bsrc + (size_t)row * K + q * 4);
        }
        CP_COMMIT();
    };

    const int ma = wm * 64 + gid;
    const int na = wn * 32 + gid;

    auto compute = [&](int s) {
#pragma unroll
        for (int ks = 0; ks < 2; ks++) {
            const int kg = ks * 2;
            uint32_t af[4][4], bf[4][2];
#pragma unroll
            for (int mi = 0; mi < 4; mi++) {
                int m = ma + mi * 16;
                af[mi][0] = __float_as_uint(As[((s * 4 + kg) * 128 + m) * 4 + tig]);
                af[mi][1] = __float_as_uint(As[((s * 4 + kg) * 128 + m + 8) * 4 + tig]);
                af[mi][2] = __float_as_uint(As[((s * 4 + kg + 1) * 128 + m) * 4 + tig]);
                af[mi][3] = __float_as_uint(As[((s * 4 + kg + 1) * 128 + m + 8) * 4 + tig]);
            }
#pragma unroll
            for (int ni = 0; ni < 4; ni++) {
                int n = na + ni * 8;
                bf[ni][0] = __float_as_uint(Bs[((s * 4 + kg) * 128 + n) * 4 + tig]);
                bf[ni][1] = __float_as_uint(Bs[((s * 4 + kg + 1) * 128 + n) * 4 + tig]);
            }
#pragma unroll
            for (int mi = 0; mi < 4; mi++)
#pragma unroll
                for (int ni = 0; ni < 4; ni++)
                    asm volatile(
                        "mma.sync.aligned.m16n8k8.row.col.f32.tf32.tf32.f32 "
                        "{%0,%1,%2,%3},{%4,%5,%6,%7},{%8,%9},{%0,%1,%2,%3};"
                        : "+f"(acc[mi][ni][0]), "+f"(acc[mi][ni][1]),
                          "+f"(acc[mi][ni][2]), "+f"(acc[mi][ni][3])
                        : "r"(af[mi][0]), "r"(af[mi][1]),
                          "r"(af[mi][2]), "r"(af[mi][3]),
                          "r"(bf[ni][0]), "r"(bf[ni][1]));
        }
    };

    issue_stage(0, 0);
    issue_stage(1, 1);
    issue_stage(2, 2);

    for (int c = 0; c < NC; c++) {
        if (c + 2 < NC)
            asm volatile("cp.async.wait_group 2;" ::: "memory");
        else if (c + 1 < NC)
            asm volatile("cp.async.wait_group 1;" ::: "memory");
        else
            asm volatile("cp.async.wait_group 0;" ::: "memory");
        __syncthreads();
        if (c + 3 < NC) issue_stage(c + 3, (c + 3) & (STAGES - 1));
        compute(c & (STAGES - 1));
    }

    // ---------------- epilogue: fused scatter from accumulators -------------
    const float qscale = 0.17677669529663687f;

    auto store_pair = [&](int m, int n, float vx, float vy) {
        vx += __ldg(&bias[n]);
        vy += __ldg(&bias[n + 1]);
        if (MODE == 0) {
            int tq = n / CCH;
            int rem = n - tq * CCH;
            int head = rem >> 5, hd = rem & 31;
            int win = m / NTOK, tokn = m - win * NTOK;
            float scl = (tq == 0) ? qscale : 1.0f;
            float* dst = (tq == 0) ? g_q : (tq == 1) ? g_k : g_v;
            size_t o = (((size_t)(win * NHEAD + head)) * NTOK + tokn) * HDIM + hd;
            *reinterpret_cast<float2*>(dst + o) = make_float2(vx * scl, vy * scl);
        } else if (MODE == 1) {
            int win = m / NTOK, tokn = m - win * NTOK;
            int b = win >> 6, widx = win & 63;
            int h = (widx >> 3) * 7 + tokn / 7 + 3; if (h >= HH)  h -= HH;
            int w = (widx & 7) * 7 + tokn % 7 + 3;  if (w >= WW2) w -= WW2;
            size_t tk = ((size_t)(b * HH + h)) * WW2 + w;
            float2 r = *reinterpret_cast<const float2*>(g_xbhwc + tk * CCH + n);
            *reinterpret_cast<float2*>(g_x2 + tk * CCH + n) =
                make_float2(vx + r.x, vy + r.y);
        } else if (MODE == 2) {
            vx = 0.5f * vx * (1.0f + erff(vx * 0.70710678118654752f));
            vy = 0.5f * vy * (1.0f + erff(vy * 0.70710678118654752f));
            *reinterpret_cast<float2*>(g_h1 + (size_t)m * MLPD + n) =
                make_float2(tf32r(vx), tf32r(vy));
        } else {
            float2 r = *reinterpret_cast<const float2*>(g_x2 + (size_t)m * CCH + n);
            *reinterpret_cast<float2*>(g_y + (size_t)m * CCH + n) =
                make_float2(vx + r.x, vy + r.y);
        }
    };

#pragma unroll
    for (int mi = 0; mi < 4; mi++) {
#pragma unroll
        for (int ni = 0; ni < 4; ni++) {
            int m = m0 + wm * 64 + mi * 16 + gid;
            int n = n0 + wn * 32 + ni * 8 + tig * 2;
            store_pair(m,     n, acc[mi][ni][0], acc[mi][ni][1]);
            store_pair(m + 8, n, acc[mi][ni][2], acc[mi][ni][3]);
        }
    }
}

// ---------------------------------------------------------------------------
// K1: LN1 + NCHW->NHWC + shifted-window partition (tf32-rounds g_xw)
// ---------------------------------------------------------------------------
__global__ void __launch_bounds__(256) k_ln1_window(
    const float* __restrict__ x, const float* __restrict__ g1,
    const float* __restrict__ b1)
{
    extern __shared__ float sm[];
    __shared__ float smu[56], srs[56];
    const int bh = blockIdx.x;
    const int b = bh / HH, h = bh % HH;
    const int tid = threadIdx.x;
    const float* xp = x + (size_t)b * CCH * (HH * WW2) + (size_t)h * WW2;

    for (int idx = tid; idx < CCH * WW2; idx += 256) {
        int c = idx / WW2, w = idx % WW2;
        sm[c * 57 + w] = xp[(size_t)c * (HH * WW2) + w];
    }
    __syncthreads();
    if (tid < WW2) {
        float s = 0.f, s2 = 0.f;
        for (int c = 0; c < CCH; c++) {
            float t = sm[c * 57 + tid];
            s += t; s2 += t * t;
        }
        float mu = s * (1.0f / CCH);
        smu[tid] = mu;
        srs[tid] = rsqrtf(s2 * (1.0f / CCH) - mu * mu + 1e-5f);
    }
    __syncthreads();

    int hp = h - 3; if (hp < 0) hp += HH;
    const int wh = hp / 7, rr = hp % 7;
    for (int idx = tid; idx < WW2 * CCH; idx += 256) {
        int w = idx / CCH, c = idx % CCH;
        float val = sm[c * 57 + w];
        size_t tok = (size_t)(b * HH + h) * WW2 + w;
        g_xbhwc[tok * CCH + c] = val;
        float nv = (val - smu[w]) * srs[w] * __ldg(&g1[c]) + __ldg(&b1[c]);
        int wp = w - 3; if (wp < 0) wp += WW2;
        int win = (b * 8 + wh) * 8 + wp / 7;
        g_xw[((size_t)win * NTOK + rr * 7 + wp % 7) * CCH + c] = tf32r(nv);
    }
}

// ---------------------------------------------------------------------------
// K3: windowed attention (tf32-rounds g_ao)
// ---------------------------------------------------------------------------
__global__ void __launch_bounds__(256) k_attn()
{
    __shared__ float sq[NTOK * 33], sk[NTOK * 33], sv[NTOK * 33];
    __shared__ float sS[NTOK * 52];
    __shared__ int   sid[NTOK];

    const int win = blockIdx.x / NHEAD;
    const int nh  = blockIdx.x % NHEAD;
    const int tid = threadIdx.x;
    const size_t base = ((size_t)(win * NHEAD + nh)) * NTOK * HDIM;

    for (int idx = tid; idx < NTOK * HDIM; idx += 256) {
        int r = idx >> 5, c = idx & 31;
        sq[r * 33 + c] = g_q[base + idx];
        sk[r * 33 + c] = g_k[base + idx];
        sv[r * 33 + c] = g_v[base + idx];
    }
    if (tid < NTOK) {
        int widx = win & 63;
        int hp = (widx >> 3) * 7 + tid / 7;
        int wp = (widx & 7) * 7 + tid % 7;
        int hr = (hp < 49) ? 0 : (hp < 53 ? 1 : 2);
        int wr = (wp < 49) ? 0 : (wp < 53 ? 1 : 2);
        sid[tid] = hr * 3 + wr;
    }
    __syncthreads();

    for (int idx = tid; idx < NTOK * NTOK; idx += 256) {
        int i = idx / NTOK, j = idx % NTOK;
        float s = 0.f;
#pragma unroll
        for (int l = 0; l < HDIM; l++) s += sq[i * 33 + l] * sk[j * 33 + l];
        if (sid[i] != sid[j]) s -= 100.0f;
        sS[i * 52 + j] = s;
    }
    __syncthreads();

    const int warp = tid >> 5, lane = tid & 31;
    for (int i = warp; i < NTOK; i += 8) {
        float mx = -1e30f;
        for (int j = lane; j < NTOK; j += 32) mx = fmaxf(mx, sS[i * 52 + j]);
#pragma unroll
        for (int o = 16; o; o >>= 1) mx = fmaxf(mx, __shfl_xor_sync(0xffffffffu, mx, o));
        float sum = 0.f;
        for (int j = lane; j < NTOK; j += 32) {
            float e = __expf(sS[i * 52 + j] - mx);
            sS[i * 52 + j] = e;
            sum += e;
        }
#pragma unroll
        for (int o = 16; o; o >>= 1) sum += __shfl_xor_sync(0xffffffffu, sum, o);
        float inv = 1.0f / sum;
        for (int j = lane; j < NTOK; j += 32) sS[i * 52 + j] *= inv;
    }
    __syncthreads();

    for (int idx = tid; idx < NTOK * HDIM; idx += 256) {
        int i = idx >> 5, d = idx & 31;
        float o = 0.f;
#pragma unroll 7
        for (int j = 0; j < NTOK; j++) o += sS[i * 52 + j] * sv[j * 33 + d];
        g_ao[((size_t)(win * NTOK + i)) * CCH + nh * HDIM + d] = tf32r(o);
    }
}

// ---------------------------------------------------------------------------
// K4: LN2 (tf32-rounds g_xn2)
// ---------------------------------------------------------------------------
__global__ void __launch_bounds__(256) k_ln2(
    const float* __restrict__ g2, const float* __restrict__ b2)
{
    const int warp = threadIdx.x >> 5, lane = threadIdx.x & 31;
    const size_t tok = (size_t)blockIdx.x * 8 + warp;
    const float* p = g_x2 + tok * CCH;
    float v[12];
    float s = 0.f, s2 = 0.f;
#pragma unroll
    for (int i = 0; i < 12; i++) {
        v[i] = p[lane + i * 32];
        s += v[i]; s2 += v[i] * v[i];
    }
#pragma unroll
    for (int o = 16; o; o >>= 1) {
        s  += __shfl_xor_sync(0xffffffffu, s,  o);
        s2 += __shfl_xor_sync(0xffffffffu, s2, o);
    }
    float mu = s * (1.0f / CCH);
    float rs = rsqrtf(s2 * (1.0f / CCH) - mu * mu + 1e-5f);
    float* q = g_xn2 + tok * CCH;
#pragma unroll
    for (int i = 0; i < 12; i++) {
        int c = lane + i * 32;
        q[c] = tf32r((v[i] - mu) * rs * __ldg(&g2[c]) + __ldg(&b2[c]));
    }
}

// ---------------------------------------------------------------------------
// K5: NHWC -> NCHW
// ---------------------------------------------------------------------------
__global__ void __launch_bounds__(256) k_tr(float* __restrict__ out)
{
    __shared__ float t[32 * 57];
    const int bh = blockIdx.x;
    const int c0 = blockIdx.y * 32;
    const int b = bh / HH, h = bh % HH;
    const float* yp = g_y + (size_t)bh * WW2 * CCH + c0;

    for (int idx = threadIdx.x; idx < WW2 * 32; idx += 256) {
        int w = idx >> 5, cc = idx & 31;
        t[cc * 57 + w] = yp[(size_t)w * CCH + cc];
    }
    __syncthreads();
    float* op = out + (size_t)b * CCH * (HH * WW2) + (size_t)c0 * (HH * WW2) + h * WW2;
    for (int idx = threadIdx.x; idx < WW2 * 32; idx += 256) {
        int cc = idx / WW2, w = idx % WW2;
        op[(size_t)cc * (HH * WW2) + w] = t[cc * 57 + w];
    }
}

// ---------------------------------------------------------------------------
extern "C" void kernel_launch(void* const* d_in, const int* in_sizes, int n_in,
                              void* d_out, int out_size)
{
    const float* x       = (const float*)d_in[0];
    const float* norm1_g = (const float*)d_in[1];
    const float* norm1_b = (const float*)d_in[2];
    const float* qkv_w   = (const float*)d_in[3];
    const float* qkv_b   = (const float*)d_in[4];
    const float* proj_w  = (const float*)d_in[5];
    const float* proj_b  = (const float*)d_in[6];
    const float* norm2_g = (const float*)d_in[7];
    const float* norm2_b = (const float*)d_in[8];
    const float* fc1_w   = (const float*)d_in[9];
    const float* fc1_b   = (const float*)d_in[10];
    const float* fc2_w   = (const float*)d_in[11];
    const float* fc2_b   = (const float*)d_in[12];

    float *p_xw, *p_ao, *p_xn2, *p_h1, *p_wqkv, *p_wproj, *p_wfc1, *p_wfc2;
    cudaGetSymbolAddress((void**)&p_xw,   g_xw);
    cudaGetSymbolAddress((void**)&p_ao,   g_ao);
    cudaGetSymbolAddress((void**)&p_xn2,  g_xn2);
    cudaGetSymbolAddress((void**)&p_h1,   g_h1);
    cudaGetSymbolAddress((void**)&p_wqkv, g_wt_qkv);
    cudaGetSymbolAddress((void**)&p_wproj,g_wt_proj);
    cudaGetSymbolAddress((void**)&p_wfc1, g_wt_fc1);
    cudaGetSymbolAddress((void**)&p_wfc2, g_wt_fc2);

    const int ln1_smem = 384 * 57 * sizeof(float);
    cudaFuncSetAttribute(k_ln1_window,
                         cudaFuncAttributeMaxDynamicSharedMemorySize, ln1_smem);
    cudaFuncSetAttribute(k_gemm_mma<0>,
                         cudaFuncAttributeMaxDynamicSharedMemorySize, GEMM_SMEM);
    cudaFuncSetAttribute(k_gemm_mma<1>,
                         cudaFuncAttributeMaxDynamicSharedMemorySize, GEMM_SMEM);
    cudaFuncSetAttribute(k_gemm_mma<2>,
                         cudaFuncAttributeMaxDynamicSharedMemorySize, GEMM_SMEM);
    cudaFuncSetAttribute(k_gemm_mma<3>,
                         cudaFuncAttributeMaxDynamicSharedMemorySize, GEMM_SMEM);

    // 0) weight prep: transpose + tf32 round
    k_wtprep<<<dim3(1152 / 32, 384 / 32), 256>>>(qkv_w, p_wqkv, 384, 1152);
    k_wtprep<<<dim3(384 / 32, 384 / 32), 256>>>(proj_w, p_wproj, 384, 384);
    k_wtprep<<<dim3(MLPD / 32, 384 / 32), 256>>>(fc1_w, p_wfc1, 384, MLPD);
    k_wtprep<<<dim3(384 / 32, MLPD / 32), 256>>>(fc2_w, p_wfc2, MLPD, 384);

    // 1) LN1 + transpose + shifted window partition
    k_ln1_window<<<16 * HH, 256, ln1_smem>>>(x, norm1_g, norm1_b);

    // 2) QKV GEMM: [50176,384] x [384,1152]
    k_gemm_mma<0><<<dim3(1152 / 128, TOK / 128), 256, GEMM_SMEM>>>(
        p_xw, p_wqkv, qkv_b, 384, 1152, 24);

    // 3) windowed attention
    k_attn<<<NWIN * NHEAD, 256>>>();

    // 4) proj GEMM + window reverse + residual
    k_gemm_mma<1><<<dim3(CCH / 128, TOK / 128), 256, GEMM_SMEM>>>(
        p_ao, p_wproj, proj_b, 384, CCH, 24);

    // 5) LN2
    k_ln2<<<TOK / 8, 256>>>(norm2_g, norm2_b);

    // 6) fc1 + GELU
    k_gemm_mma<2><<<dim3(MLPD / 128, TOK / 128), 256, GEMM_SMEM>>>(
        p_xn2, p_wfc1, fc1_b, 384, MLPD, 24);

    // 7) fc2 + residual
    k_gemm_mma<3><<<dim3(CCH / 128, TOK / 128), 256, GEMM_SMEM>>>(
        p_h1, p_wfc2, fc2_b, 1536, CCH, 96);

    // 8) NHWC -> NCHW
    k_tr<<<dim3(16 * HH, CCH / 32), 256>>>((float*)d_out);
}

// round 9
// speedup vs baseline: 1.6429x; 1.6429x over previous
#include <cuda_runtime.h>
#include <cuda_bf16.h>
#include <math.h>
#include <stdint.h>

// ---------------------------------------------------------------------------
// Swin block: B=16, C=384, H=W=56, NH=12, WS=7, SS=3, MLP=1536
// GEMMs: mma.sync m16n8k16 bf16 (fp32 accum), 128x128 CTA / 64x32 warp,
// k-chunk 32, reg double-buffer (R6 skeleton). Attention stays fp32.
// ---------------------------------------------------------------------------
#define TOK   50176
#define CCH   384
#define HH    56
#define WW2   56
#define NWIN  1024
#define NTOK  49
#define NHEAD 12
#define HDIM  32
#define MLPD  1536

// Scratch
__device__ float g_xbhwc[TOK * CCH];
__device__ __nv_bfloat16 g_xw [TOK * CCH];     // LN1 out (A of QKV)
__device__ float g_q  [TOK * CCH];
__device__ float g_k  [TOK * CCH];
__device__ float g_v  [TOK * CCH];
__device__ __nv_bfloat16 g_ao [TOK * CCH];     // attn out (A of proj)
__device__ float g_x2 [TOK * CCH];
__device__ __nv_bfloat16 g_xn2[TOK * CCH];     // LN2 out (A of fc1)
__device__ __nv_bfloat16 g_h1 [TOK * MLPD];    // gelu out (A of fc2)
__device__ float g_y  [TOK * CCH];
// bf16 transposed weights [N][K]
__device__ __nv_bfloat16 g_wt_qkv [1152 * 384];
__device__ __nv_bfloat16 g_wt_proj[384 * 384];
__device__ __nv_bfloat16 g_wt_fc1 [MLPD * 384];
__device__ __nv_bfloat16 g_wt_fc2 [384 * MLPD];

// ---------------------------------------------------------------------------
// K0: weight prep: W[K][N] fp32 -> Wt[N][K] bf16
// ---------------------------------------------------------------------------
__global__ void __launch_bounds__(256) k_wtprep(const float* __restrict__ W,
                                                __nv_bfloat16* __restrict__ Wt,
                                                int K, int N)
{
    __shared__ float t[32][33];
    const int n0 = blockIdx.x * 32, k0 = blockIdx.y * 32;
    const int lx = threadIdx.x & 31, ly = threadIdx.x >> 5;
#pragma unroll
    for (int i = 0; i < 4; i++)
        t[ly + i * 8][lx] = W[(size_t)(k0 + ly + i * 8) * N + n0 + lx];
    __syncthreads();
#pragma unroll
    for (int i = 0; i < 4; i++)
        Wt[(size_t)(n0 + ly + i * 8) * K + k0 + lx] =
            __float2bfloat16_rn(t[lx][ly + i * 8]);
}

// ---------------------------------------------------------------------------
// bf16 mma GEMM: C = A[M,K] * Bt[N,K]^T, fp32 accum.
// CTA 128x128, 8 warps (2M x 4N), warp 64x32, k-chunk 32, reg double-buffer.
// Crosswise smem: uint32 As[stage][kg][x][4] where element (k, x) pair
// (k = kg*8 + 2*q, +1) lives at [kg][x][q]  -> fragment LDS.32 = lanes cover
// one contiguous 128B line (m from gid, q from tig). 16B global chunks map to
// 16B contiguous smem chunks (pure memcpy, no conversion).
// MODE 0: QKV split  1: proj+winrev+residual  2: fc1+GELU  3: fc2+residual
// ---------------------------------------------------------------------------
template <int MODE>
__global__ void __launch_bounds__(256, 2) k_gemm_bf16(
    const __nv_bfloat16* __restrict__ A, const __nv_bfloat16* __restrict__ Bt,
    const float* __restrict__ bias, int K, int N, int NC)
{
    __shared__ uint32_t As[2][4][128][4];   // 16 KB
    __shared__ uint32_t Bs[2][4][128][4];   // 16 KB

    const int tid = threadIdx.x;
    const int wid = tid >> 5, lane = tid & 31;
    const int gid = lane >> 2, tig = lane & 3;
    const int wm = wid & 1, wn = wid >> 1;       // 2 x 4 warp grid
    const int m0 = blockIdx.y * 128, n0 = blockIdx.x * 128;

    float acc[4][4][4];
#pragma unroll
    for (int a = 0; a < 4; a++)
#pragma unroll
        for (int b = 0; b < 4; b++)
#pragma unroll
            for (int c = 0; c < 4; c++) acc[a][b][c] = 0.f;

    // staging: idx = t*256 + tid in [0,512): row = idx>>2, kg = idx&3
    const int st_row = tid >> 2;                 // 0..63 (+64 for t=1)
    const int st_kg = tid & 3;

    uint4 la[2], lb[2];

    auto ldg_chunk = [&](int c) {
#pragma unroll
        for (int t = 0; t < 2; t++) {
            int row = t * 64 + st_row;
            la[t] = *reinterpret_cast<const uint4*>(
                A + (size_t)(m0 + row) * K + c * 32 + st_kg * 8);
            lb[t] = *reinterpret_cast<const uint4*>(
                Bt + (size_t)(n0 + row) * K + c * 32 + st_kg * 8);
        }
    };
    auto sts_chunk = [&](int s) {
#pragma unroll
        for (int t = 0; t < 2; t++) {
            int row = t * 64 + st_row;
            *reinterpret_cast<uint4*>(&As[s][st_kg][row][0]) = la[t];
            *reinterpret_cast<uint4*>(&Bs[s][st_kg][row][0]) = lb[t];
        }
    };

    const int ma = wm * 64 + gid;
    const int na = wn * 32 + gid;

    auto compute = [&](int s) {
#pragma unroll
        for (int ks = 0; ks < 2; ks++) {
            const int kg = ks * 2;
            uint32_t af[4][4], bf[4][2];
#pragma unroll
            for (int mi = 0; mi < 4; mi++) {
                int m = ma + mi * 16;
                af[mi][0] = As[s][kg][m][tig];
                af[mi][1] = As[s][kg][m + 8][tig];
                af[mi][2] = As[s][kg + 1][m][tig];
                af[mi][3] = As[s][kg + 1][m + 8][tig];
            }
#pragma unroll
            for (int ni = 0; ni < 4; ni++) {
                int n = na + ni * 8;
                bf[ni][0] = Bs[s][kg][n][tig];
                bf[ni][1] = Bs[s][kg + 1][n][tig];
            }
#pragma unroll
            for (int mi = 0; mi < 4; mi++)
#pragma unroll
                for (int ni = 0; ni < 4; ni++)
                    asm volatile(
                        "mma.sync.aligned.m16n8k16.row.col.f32.bf16.bf16.f32 "
                        "{%0,%1,%2,%3},{%4,%5,%6,%7},{%8,%9},{%0,%1,%2,%3};"
                        : "+f"(acc[mi][ni][0]), "+f"(acc[mi][ni][1]),
                          "+f"(acc[mi][ni][2]), "+f"(acc[mi][ni][3])
                        : "r"(af[mi][0]), "r"(af[mi][1]),
                          "r"(af[mi][2]), "r"(af[mi][3]),
                          "r"(bf[ni][0]), "r"(bf[ni][1]));
        }
    };

    int s = 0;
    ldg_chunk(0);
    sts_chunk(0);
    __syncthreads();
    for (int c = 0; c < NC; c++) {
        if (c + 1 < NC) ldg_chunk(c + 1);
        compute(s);
        if (c + 1 < NC) sts_chunk(s ^ 1);
        __syncthreads();
        s ^= 1;
    }

    // ---------------- epilogue: fused scatter from accumulators -------------
    const float qscale = 0.17677669529663687f;

    auto store_pair = [&](int m, int n, float vx, float vy) {
        vx += __ldg(&bias[n]);
        vy += __ldg(&bias[n + 1]);
        if (MODE == 0) {
            int tq = n / CCH;
            int rem = n - tq * CCH;
            int head = rem >> 5, hd = rem & 31;
            int win = m / NTOK, tokn = m - win * NTOK;
            float scl = (tq == 0) ? qscale : 1.0f;
            float* dst = (tq == 0) ? g_q : (tq == 1) ? g_k : g_v;
            size_t o = (((size_t)(win * NHEAD + head)) * NTOK + tokn) * HDIM + hd;
            *reinterpret_cast<float2*>(dst + o) = make_float2(vx * scl, vy * scl);
        } else if (MODE == 1) {
            int win = m / NTOK, tokn = m - win * NTOK;
            int b = win >> 6, widx = win & 63;
            int h = (widx >> 3) * 7 + tokn / 7 + 3; if (h >= HH)  h -= HH;
            int w = (widx & 7) * 7 + tokn % 7 + 3;  if (w >= WW2) w -= WW2;
            size_t tk = ((size_t)(b * HH + h)) * WW2 + w;
            float2 r = *reinterpret_cast<const float2*>(g_xbhwc + tk * CCH + n);
            *reinterpret_cast<float2*>(g_x2 + tk * CCH + n) =
                make_float2(vx + r.x, vy + r.y);
        } else if (MODE == 2) {
            vx = 0.5f * vx * (1.0f + erff(vx * 0.70710678118654752f));
            vy = 0.5f * vy * (1.0f + erff(vy * 0.70710678118654752f));
            *reinterpret_cast<__nv_bfloat162*>(g_h1 + (size_t)m * MLPD + n) =
                __floats2bfloat162_rn(vx, vy);
        } else {
            float2 r = *reinterpret_cast<const float2*>(g_x2 + (size_t)m * CCH + n);
            *reinterpret_cast<float2*>(g_y + (size_t)m * CCH + n) =
                make_float2(vx + r.x, vy + r.y);
        }
    };

#pragma unroll
    for (int mi = 0; mi < 4; mi++) {
#pragma unroll
        for (int ni = 0; ni < 4; ni++) {
            int m = m0 + wm * 64 + mi * 16 + gid;
            int n = n0 + wn * 32 + ni * 8 + tig * 2;
            store_pair(m,     n, acc[mi][ni][0], acc[mi][ni][1]);
            store_pair(m + 8, n, acc[mi][ni][2], acc[mi][ni][3]);
        }
    }
}

// ---------------------------------------------------------------------------
// K1: LN1 + NCHW->NHWC + shifted-window partition (bf16 out for GEMM A)
// ---------------------------------------------------------------------------
__global__ void __launch_bounds__(256) k_ln1_window(
    const float* __restrict__ x, const float* __restrict__ g1,
    const float* __restrict__ b1)
{
    extern __shared__ float sm[];
    __shared__ float smu[56], srs[56];
    const int bh = blockIdx.x;
    const int b = bh / HH, h = bh % HH;
    const int tid = threadIdx.x;
    const float* xp = x + (size_t)b * CCH * (HH * WW2) + (size_t)h * WW2;

    for (int idx = tid; idx < CCH * WW2; idx += 256) {
        int c = idx / WW2, w = idx % WW2;
        sm[c * 57 + w] = xp[(size_t)c * (HH * WW2) + w];
    }
    __syncthreads();
    if (tid < WW2) {
        float s = 0.f, s2 = 0.f;
        for (int c = 0; c < CCH; c++) {
            float t = sm[c * 57 + tid];
            s += t; s2 += t * t;
        }
        float mu = s * (1.0f / CCH);
        smu[tid] = mu;
        srs[tid] = rsqrtf(s2 * (1.0f / CCH) - mu * mu + 1e-5f);
    }
    __syncthreads();

    int hp = h - 3; if (hp < 0) hp += HH;
    const int wh = hp / 7, rr = hp % 7;
    for (int idx = tid; idx < WW2 * CCH; idx += 256) {
        int w = idx / CCH, c = idx % CCH;
        float val = sm[c * 57 + w];
        size_t tok = (size_t)(b * HH + h) * WW2 + w;
        g_xbhwc[tok * CCH + c] = val;
        float nv = (val - smu[w]) * srs[w] * __ldg(&g1[c]) + __ldg(&b1[c]);
        int wp = w - 3; if (wp < 0) wp += WW2;
        int win = (b * 8 + wh) * 8 + wp / 7;
        g_xw[((size_t)win * NTOK + rr * 7 + wp % 7) * CCH + c] =
            __float2bfloat16_rn(nv);
    }
}

// ---------------------------------------------------------------------------
// K3: windowed attention (fp32 math, bf16 out)
// ---------------------------------------------------------------------------
__global__ void __launch_bounds__(256) k_attn()
{
    __shared__ float sq[NTOK * 33], sk[NTOK * 33], sv[NTOK * 33];
    __shared__ float sS[NTOK * 52];
    __shared__ int   sid[NTOK];

    const int win = blockIdx.x / NHEAD;
    const int nh  = blockIdx.x % NHEAD;
    const int tid = threadIdx.x;
    const size_t base = ((size_t)(win * NHEAD + nh)) * NTOK * HDIM;

    for (int idx = tid; idx < NTOK * HDIM; idx += 256) {
        int r = idx >> 5, c = idx & 31;
        sq[r * 33 + c] = g_q[base + idx];
        sk[r * 33 + c] = g_k[base + idx];
        sv[r * 33 + c] = g_v[base + idx];
    }
    if (tid < NTOK) {
        int widx = win & 63;
        int hp = (widx >> 3) * 7 + tid / 7;
        int wp = (widx & 7) * 7 + tid % 7;
        int hr = (hp < 49) ? 0 : (hp < 53 ? 1 : 2);
        int wr = (wp < 49) ? 0 : (wp < 53 ? 1 : 2);
        sid[tid] = hr * 3 + wr;
    }
    __syncthreads();

    for (int idx = tid; idx < NTOK * NTOK; idx += 256) {
        int i = idx / NTOK, j = idx % NTOK;
        float s = 0.f;
#pragma unroll
        for (int l = 0; l < HDIM; l++) s += sq[i * 33 + l] * sk[j * 33 + l];
        if (sid[i] != sid[j]) s -= 100.0f;
        sS[i * 52 + j] = s;
    }
    __syncthreads();

    const int warp = tid >> 5, lane = tid & 31;
    for (int i = warp; i < NTOK; i += 8) {
        float mx = -1e30f;
        for (int j = lane; j < NTOK; j += 32) mx = fmaxf(mx, sS[i * 52 + j]);
#pragma unroll
        for (int o = 16; o; o >>= 1) mx = fmaxf(mx, __shfl_xor_sync(0xffffffffu, mx, o));
        float sum = 0.f;
        for (int j = lane; j < NTOK; j += 32) {
            float e = __expf(sS[i * 52 + j] - mx);
            sS[i * 52 + j] = e;
            sum += e;
        }
#pragma unroll
        for (int o = 16; o; o >>= 1) sum += __shfl_xor_sync(0xffffffffu, sum, o);
        float inv = 1.0f / sum;
        for (int j = lane; j < NTOK; j += 32) sS[i * 52 + j] *= inv;
    }
    __syncthreads();

    for (int idx = tid; idx < NTOK * HDIM; idx += 256) {
        int i = idx >> 5, d = idx & 31;
        float o = 0.f;
#pragma unroll 7
        for (int j = 0; j < NTOK; j++) o += sS[i * 52 + j] * sv[j * 33 + d];
        g_ao[((size_t)(win * NTOK + i)) * CCH + nh * HDIM + d] =
            __float2bfloat16_rn(o);
    }
}

// ---------------------------------------------------------------------------
// K4: LN2 (bf16 out)
// ---------------------------------------------------------------------------
__global__ void __launch_bounds__(256) k_ln2(
    const float* __restrict__ g2, const float* __restrict__ b2)
{
    const int warp = threadIdx.x >> 5, lane = threadIdx.x & 31;
    const size_t tok = (size_t)blockIdx.x * 8 + warp;
    const float* p = g_x2 + tok * CCH;
    float v[12];
    float s = 0.f, s2 = 0.f;
#pragma unroll
    for (int i = 0; i < 12; i++) {
        v[i] = p[lane + i * 32];
        s += v[i]; s2 += v[i] * v[i];
    }
#pragma unroll
    for (int o = 16; o; o >>= 1) {
        s  += __shfl_xor_sync(0xffffffffu, s,  o);
        s2 += __shfl_xor_sync(0xffffffffu, s2, o);
    }
    float mu = s * (1.0f / CCH);
    float rs = rsqrtf(s2 * (1.0f / CCH) - mu * mu + 1e-5f);
    __nv_bfloat16* q = g_xn2 + tok * CCH;
#pragma unroll
    for (int i = 0; i < 12; i++) {
        int c = lane + i * 32;
        q[c] = __float2bfloat16_rn(
            (v[i] - mu) * rs * __ldg(&g2[c]) + __ldg(&b2[c]));
    }
}

// ---------------------------------------------------------------------------
// K5: NHWC -> NCHW
// ---------------------------------------------------------------------------
__global__ void __launch_bounds__(256) k_tr(float* __restrict__ out)
{
    __shared__ float t[32 * 57];
    const int bh = blockIdx.x;
    const int c0 = blockIdx.y * 32;
    const int b = bh / HH, h = bh % HH;
    const float* yp = g_y + (size_t)bh * WW2 * CCH + c0;

    for (int idx = threadIdx.x; idx < WW2 * 32; idx += 256) {
        int w = idx >> 5, cc = idx & 31;
        t[cc * 57 + w] = yp[(size_t)w * CCH + cc];
    }
    __syncthreads();
    float* op = out + (size_t)b * CCH * (HH * WW2) + (size_t)c0 * (HH * WW2) + h * WW2;
    for (int idx = threadIdx.x; idx < WW2 * 32; idx += 256) {
        int cc = idx / WW2, w = idx % WW2;
        op[(size_t)cc * (HH * WW2) + w] = t[cc * 57 + w];
    }
}

// ---------------------------------------------------------------------------
extern "C" void kernel_launch(void* const* d_in, const int* in_sizes, int n_in,
                              void* d_out, int out_size)
{
    const float* x       = (const float*)d_in[0];
    const float* norm1_g = (const float*)d_in[1];
    const float* norm1_b = (const float*)d_in[2];
    const float* qkv_w   = (const float*)d_in[3];
    const float* qkv_b   = (const float*)d_in[4];
    const float* proj_w  = (const float*)d_in[5];
    const float* proj_b  = (const float*)d_in[6];
    const float* norm2_g = (const float*)d_in[7];
    const float* norm2_b = (const float*)d_in[8];
    const float* fc1_w   = (const float*)d_in[9];
    const float* fc1_b   = (const float*)d_in[10];
    const float* fc2_w   = (const float*)d_in[11];
    const float* fc2_b   = (const float*)d_in[12];

    __nv_bfloat16 *p_xw, *p_ao, *p_xn2, *p_h1;
    __nv_bfloat16 *p_wqkv, *p_wproj, *p_wfc1, *p_wfc2;
    cudaGetSymbolAddress((void**)&p_xw,   g_xw);
    cudaGetSymbolAddress((void**)&p_ao,   g_ao);
    cudaGetSymbolAddress((void**)&p_xn2,  g_xn2);
    cudaGetSymbolAddress((void**)&p_h1,   g_h1);
    cudaGetSymbolAddress((void**)&p_wqkv, g_wt_qkv);
    cudaGetSymbolAddress((void**)&p_wproj,g_wt_proj);
    cudaGetSymbolAddress((void**)&p_wfc1, g_wt_fc1);
    cudaGetSymbolAddress((void**)&p_wfc2, g_wt_fc2);

    const int ln1_smem = 384 * 57 * sizeof(float);
    cudaFuncSetAttribute(k_ln1_window,
                         cudaFuncAttributeMaxDynamicSharedMemorySize, ln1_smem);

    // 0) weight prep: transpose + bf16
    k_wtprep<<<dim3(1152 / 32, 384 / 32), 256>>>(qkv_w, p_wqkv, 384, 1152);
    k_wtprep<<<dim3(384 / 32, 384 / 32), 256>>>(proj_w, p_wproj, 384, 384);
    k_wtprep<<<dim3(MLPD / 32, 384 / 32), 256>>>(fc1_w, p_wfc1, 384, MLPD);
    k_wtprep<<<dim3(384 / 32, MLPD / 32), 256>>>(fc2_w, p_wfc2, MLPD, 384);

    // 1) LN1 + transpose + shifted window partition
    k_ln1_window<<<16 * HH, 256, ln1_smem>>>(x, norm1_g, norm1_b);

    // 2) QKV GEMM: [50176,384] x [384,1152]
    k_gemm_bf16<0><<<dim3(1152 / 128, TOK / 128), 256>>>(
        p_xw, p_wqkv, qkv_b, 384, 1152, 12);

    // 3) windowed attention
    k_attn<<<NWIN * NHEAD, 256>>>();

    // 4) proj GEMM + window reverse + residual
    k_gemm_bf16<1><<<dim3(CCH / 128, TOK / 128), 256>>>(
        p_ao, p_wproj, proj_b, 384, CCH, 12);

    // 5) LN2
    k_ln2<<<TOK / 8, 256>>>(norm2_g, norm2_b);

    // 6) fc1 + GELU
    k_gemm_bf16<2><<<dim3(MLPD / 128, TOK / 128), 256>>>(
        p_xn2, p_wfc1, fc1_b, 384, MLPD, 12);

    // 7) fc2 + residual
    k_gemm_bf16<3><<<dim3(CCH / 128, TOK / 128), 256>>>(
        p_h1, p_wfc2, fc2_b, 1536, CCH, 48);

    // 8) NHWC -> NCHW
    k_tr<<<dim3(16 * HH, CCH / 32), 256>>>((float*)d_out);
}

// round 10
// speedup vs baseline: 1.7075x; 1.0393x over previous
#include <cuda_runtime.h>
#include <cuda_bf16.h>
#include <math.h>
#include <stdint.h>

// ---------------------------------------------------------------------------
// Swin block: B=16, C=384, H=W=56, NH=12, WS=7, SS=3, MLP=1536
// GEMMs: mma.sync m16n8k16 bf16 (fp32 accum), 128x128 CTA / 64x32 warp,
// k-chunk 32, reg double-buffer, ldmatrix fragment loads.
// ---------------------------------------------------------------------------
#define TOK   50176
#define CCH   384
#define HH    56
#define WW2   56
#define NWIN  1024
#define NTOK  49
#define NHEAD 12
#define HDIM  32
#define MLPD  1536

// Scratch
__device__ float g_xbhwc[TOK * CCH];
__device__ __nv_bfloat16 g_xw [TOK * CCH];     // LN1 out (A of QKV)
__device__ float g_q  [TOK * CCH];
__device__ float g_k  [TOK * CCH];
__device__ float g_v  [TOK * CCH];
__device__ __nv_bfloat16 g_ao [TOK * CCH];     // attn out (A of proj)
__device__ float g_x2 [TOK * CCH];
__device__ __nv_bfloat16 g_xn2[TOK * CCH];     // LN2 out (A of fc1)
__device__ __nv_bfloat16 g_h1 [TOK * MLPD];    // gelu out (A of fc2)
__device__ float g_y  [TOK * CCH];
// bf16 transposed weights [N][K]
__device__ __nv_bfloat16 g_wt_qkv [1152 * 384];
__device__ __nv_bfloat16 g_wt_proj[384 * 384];
__device__ __nv_bfloat16 g_wt_fc1 [MLPD * 384];
__device__ __nv_bfloat16 g_wt_fc2 [384 * MLPD];

__device__ __forceinline__ uint32_t smem_u32(const void* p) {
    uint32_t a;
    asm("{ .reg .u64 t; cvta.to.shared.u64 t, %1; cvt.u32.u64 %0, t; }"
        : "=r"(a) : "l"(p));
    return a;
}

// ---------------------------------------------------------------------------
// K0: weight prep: W[K][N] fp32 -> Wt[N][K] bf16
// ---------------------------------------------------------------------------
__global__ void __launch_bounds__(256) k_wtprep(const float* __restrict__ W,
                                                __nv_bfloat16* __restrict__ Wt,
                                                int K, int N)
{
    __shared__ float t[32][33];
    const int n0 = blockIdx.x * 32, k0 = blockIdx.y * 32;
    const int lx = threadIdx.x & 31, ly = threadIdx.x >> 5;
#pragma unroll
    for (int i = 0; i < 4; i++)
        t[ly + i * 8][lx] = W[(size_t)(k0 + ly + i * 8) * N + n0 + lx];
    __syncthreads();
#pragma unroll
    for (int i = 0; i < 4; i++)
        Wt[(size_t)(n0 + ly + i * 8) * K + k0 + lx] =
            __float2bfloat16_rn(t[lx][ly + i * 8]);
}

// ---------------------------------------------------------------------------
// bf16 mma GEMM: C = A[M,K] * Bt[N,K]^T, fp32 accum.
// CTA 128x128, 8 warps (2M x 4N), warp 64x32, k-chunk 32, reg double-buffer.
// Crosswise smem: As[stage][kg][row][q] (uint32 = bf16 pair k=kg*8+2q,+1).
// (kg,row) lines are contiguous 16B -> native ldmatrix.m8n8.b16 row format:
//   A frags: 1 LDSM.x4 per (mi,ks);  B frags: 1 LDSM.x2 per (ni,ks).
// MODE 0: QKV split  1: proj+winrev+residual  2: fc1+GELU  3: fc2+residual
// ---------------------------------------------------------------------------
template <int MODE>
__global__ void __launch_bounds__(256, 2) k_gemm_bf16(
    const __nv_bfloat16* __restrict__ A, const __nv_bfloat16* __restrict__ Bt,
    const float* __restrict__ bias, int K, int N, int NC)
{
    __shared__ uint32_t As[2][4][128][4];   // 16 KB
    __shared__ uint32_t Bs[2][4][128][4];   // 16 KB

    const int tid = threadIdx.x;
    const int wid = tid >> 5, lane = tid & 31;
    const int gid = lane >> 2, tig = lane & 3;
    const int wm = wid & 1, wn = wid >> 1;       // 2 x 4 warp grid
    const int m0 = blockIdx.y * 128, n0 = blockIdx.x * 128;

    const uint32_t sA = smem_u32(As), sB = smem_u32(Bs);
    // ldmatrix lane-address components (byte offsets built per use)
    const int rowA = wm * 64 + ((lane >> 3) & 1) * 8 + (lane & 7);
    const int kgoA = lane >> 4;                  // 0: kg, 1: kg+1
    const int rowB = wn * 32 + (lane & 7);
    const int kgoB = (lane >> 3) & 1;

    float acc[4][4][4];
#pragma unroll
    for (int a = 0; a < 4; a++)
#pragma unroll
        for (int b = 0; b < 4; b++)
#pragma unroll
            for (int c = 0; c < 4; c++) acc[a][b][c] = 0.f;

    // staging: idx = t*256 + tid: row = idx>>2, kg = idx&3
    const int st_row = tid >> 2;
    const int st_kg = tid & 3;

    uint4 la[2], lb[2];

    auto ldg_chunk = [&](int c) {
#pragma unroll
        for (int t = 0; t < 2; t++) {
            int row = t * 64 + st_row;
            la[t] = *reinterpret_cast<const uint4*>(
                A + (size_t)(m0 + row) * K + c * 32 + st_kg * 8);
            lb[t] = *reinterpret_cast<const uint4*>(
                Bt + (size_t)(n0 + row) * K + c * 32 + st_kg * 8);
        }
    };
    auto sts_chunk = [&](int s) {
#pragma unroll
        for (int t = 0; t < 2; t++) {
            int row = t * 64 + st_row;
            *reinterpret_cast<uint4*>(&As[s][st_kg][row][0]) = la[t];
            *reinterpret_cast<uint4*>(&Bs[s][st_kg][row][0]) = lb[t];
        }
    };

    auto compute = [&](int s) {
#pragma unroll
        for (int ks = 0; ks < 2; ks++) {
            uint32_t af[4][4], bf[4][2];
#pragma unroll
            for (int mi = 0; mi < 4; mi++) {
                uint32_t addr = sA +
                    (uint32_t)(((s * 4 + ks * 2 + kgoA) * 128 +
                                rowA + mi * 16) * 16);
                asm volatile(
                    "ldmatrix.sync.aligned.m8n8.x4.shared.b16 "
                    "{%0,%1,%2,%3}, [%4];"
                    : "=r"(af[mi][0]), "=r"(af[mi][1]),
                      "=r"(af[mi][2]), "=r"(af[mi][3])
                    : "r"(addr));
            }
#pragma unroll
            for (int ni = 0; ni < 4; ni++) {
                uint32_t addr = sB +
                    (uint32_t)(((s * 4 + ks * 2 + kgoB) * 128 +
                                rowB + ni * 8) * 16);
                asm volatile(
                    "ldmatrix.sync.aligned.m8n8.x2.shared.b16 "
                    "{%0,%1}, [%2];"
                    : "=r"(bf[ni][0]), "=r"(bf[ni][1])
                    : "r"(addr));
            }
#pragma unroll
            for (int mi = 0; mi < 4; mi++)
#pragma unroll
                for (int ni = 0; ni < 4; ni++)
                    asm volatile(
                        "mma.sync.aligned.m16n8k16.row.col.f32.bf16.bf16.f32 "
                        "{%0,%1,%2,%3},{%4,%5,%6,%7},{%8,%9},{%0,%1,%2,%3};"
                        : "+f"(acc[mi][ni][0]), "+f"(acc[mi][ni][1]),
                          "+f"(acc[mi][ni][2]), "+f"(acc[mi][ni][3])
                        : "r"(af[mi][0]), "r"(af[mi][1]),
                          "r"(af[mi][2]), "r"(af[mi][3]),
                          "r"(bf[ni][0]), "r"(bf[ni][1]));
        }
    };

    int s = 0;
    ldg_chunk(0);
    sts_chunk(0);
    __syncthreads();
    for (int c = 0; c < NC; c++) {
        if (c + 1 < NC) ldg_chunk(c + 1);
        compute(s);
        if (c + 1 < NC) sts_chunk(s ^ 1);
        __syncthreads();
        s ^= 1;
    }

    // ---------------- epilogue: fused scatter from accumulators -------------
    const float qscale = 0.17677669529663687f;

    auto store_pair = [&](int m, int n, float vx, float vy) {
        vx += __ldg(&bias[n]);
        vy += __ldg(&bias[n + 1]);
        if (MODE == 0) {
            int tq = n / CCH;
            int rem = n - tq * CCH;
            int head = rem >> 5, hd = rem & 31;
            int win = m / NTOK, tokn = m - win * NTOK;
            float scl = (tq == 0) ? qscale : 1.0f;
            float* dst = (tq == 0) ? g_q : (tq == 1) ? g_k : g_v;
            size_t o = (((size_t)(win * NHEAD + head)) * NTOK + tokn) * HDIM + hd;
            *reinterpret_cast<float2*>(dst + o) = make_float2(vx * scl, vy * scl);
        } else if (MODE == 1) {
            int win = m / NTOK, tokn = m - win * NTOK;
            int b = win >> 6, widx = win & 63;
            int h = (widx >> 3) * 7 + tokn / 7 + 3; if (h >= HH)  h -= HH;
            int w = (widx & 7) * 7 + tokn % 7 + 3;  if (w >= WW2) w -= WW2;
            size_t tk = ((size_t)(b * HH + h)) * WW2 + w;
            float2 r = *reinterpret_cast<const float2*>(g_xbhwc + tk * CCH + n);
            *reinterpret_cast<float2*>(g_x2 + tk * CCH + n) =
                make_float2(vx + r.x, vy + r.y);
        } else if (MODE == 2) {
            vx = 0.5f * vx * (1.0f + erff(vx * 0.70710678118654752f));
            vy = 0.5f * vy * (1.0f + erff(vy * 0.70710678118654752f));
            *reinterpret_cast<__nv_bfloat162*>(g_h1 + (size_t)m * MLPD + n) =
                __floats2bfloat162_rn(vx, vy);
        } else {
            float2 r = *reinterpret_cast<const float2*>(g_x2 + (size_t)m * CCH + n);
            *reinterpret_cast<float2*>(g_y + (size_t)m * CCH + n) =
                make_float2(vx + r.x, vy + r.y);
        }
    };

#pragma unroll
    for (int mi = 0; mi < 4; mi++) {
#pragma unroll
        for (int ni = 0; ni < 4; ni++) {
            int m = m0 + wm * 64 + mi * 16 + gid;
            int n = n0 + wn * 32 + ni * 8 + tig * 2;
            store_pair(m,     n, acc[mi][ni][0], acc[mi][ni][1]);
            store_pair(m + 8, n, acc[mi][ni][2], acc[mi][ni][3]);
        }
    }
}

// ---------------------------------------------------------------------------
// K1: LN1 + NCHW->NHWC + shifted-window partition (bf16 out for GEMM A)
// ---------------------------------------------------------------------------
__global__ void __launch_bounds__(256) k_ln1_window(
    const float* __restrict__ x, const float* __restrict__ g1,
    const float* __restrict__ b1)
{
    extern __shared__ float sm[];
    __shared__ float smu[56], srs[56];
    const int bh = blockIdx.x;
    const int b = bh / HH, h = bh % HH;
    const int tid = threadIdx.x;
    const float* xp = x + (size_t)b * CCH * (HH * WW2) + (size_t)h * WW2;

    for (int idx = tid; idx < CCH * WW2; idx += 256) {
        int c = idx / WW2, w = idx % WW2;
        sm[c * 57 + w] = xp[(size_t)c * (HH * WW2) + w];
    }
    __syncthreads();
    if (tid < WW2) {
        float s = 0.f, s2 = 0.f;
        for (int c = 0; c < CCH; c++) {
            float t = sm[c * 57 + tid];
            s += t; s2 += t * t;
        }
        float mu = s * (1.0f / CCH);
        smu[tid] = mu;
        srs[tid] = rsqrtf(s2 * (1.0f / CCH) - mu * mu + 1e-5f);
    }
    __syncthreads();

    int hp = h - 3; if (hp < 0) hp += HH;
    const int wh = hp / 7, rr = hp % 7;
    for (int idx = tid; idx < WW2 * CCH; idx += 256) {
        int w = idx / CCH, c = idx % CCH;
        float val = sm[c * 57 + w];
        size_t tok = (size_t)(b * HH + h) * WW2 + w;
        g_xbhwc[tok * CCH + c] = val;
        float nv = (val - smu[w]) * srs[w] * __ldg(&g1[c]) + __ldg(&b1[c]);
        int wp = w - 3; if (wp < 0) wp += WW2;
        int win = (b * 8 + wh) * 8 + wp / 7;
        g_xw[((size_t)win * NTOK + rr * 7 + wp % 7) * CCH + c] =
            __float2bfloat16_rn(nv);
    }
}

// ---------------------------------------------------------------------------
// K3: windowed attention (fp32 math, bf16 out)
// ---------------------------------------------------------------------------
__global__ void __launch_bounds__(256) k_attn()
{
    __shared__ float sq[NTOK * 33], sk[NTOK * 33], sv[NTOK * 33];
    __shared__ float sS[NTOK * 52];
    __shared__ int   sid[NTOK];

    const int win = blockIdx.x / NHEAD;
    const int nh  = blockIdx.x % NHEAD;
    const int tid = threadIdx.x;
    const size_t base = ((size_t)(win * NHEAD + nh)) * NTOK * HDIM;

    for (int idx = tid; idx < NTOK * HDIM; idx += 256) {
        int r = idx >> 5, c = idx & 31;
        sq[r * 33 + c] = g_q[base + idx];
        sk[r * 33 + c] = g_k[base + idx];
        sv[r * 33 + c] = g_v[base + idx];
    }
    if (tid < NTOK) {
        int widx = win & 63;
        int hp = (widx >> 3) * 7 + tid / 7;
        int wp = (widx & 7) * 7 + tid % 7;
        int hr = (hp < 49) ? 0 : (hp < 53 ? 1 : 2);
        int wr = (wp < 49) ? 0 : (wp < 53 ? 1 : 2);
        sid[tid] = hr * 3 + wr;
    }
    __syncthreads();

    for (int idx = tid; idx < NTOK * NTOK; idx += 256) {
        int i = idx / NTOK, j = idx % NTOK;
        float s = 0.f;
#pragma unroll
        for (int l = 0; l < HDIM; l++) s += sq[i * 33 + l] * sk[j * 33 + l];
        if (sid[i] != sid[j]) s -= 100.0f;
        sS[i * 52 + j] = s;
    }
    __syncthreads();

    const int warp = tid >> 5, lane = tid & 31;
    for (int i = warp; i < NTOK; i += 8) {
        float mx = -1e30f;
        for (int j = lane; j < NTOK; j += 32) mx = fmaxf(mx, sS[i * 52 + j]);
#pragma unroll
        for (int o = 16; o; o >>= 1) mx = fmaxf(mx, __shfl_xor_sync(0xffffffffu, mx, o));
        float sum = 0.f;
        for (int j = lane; j < NTOK; j += 32) {
            float e = __expf(sS[i * 52 + j] - mx);
            sS[i * 52 + j] = e;
            sum += e;
        }
#pragma unroll
        for (int o = 16; o; o >>= 1) sum += __shfl_xor_sync(0xffffffffu, sum, o);
        float inv = 1.0f / sum;
        for (int j = lane; j < NTOK; j += 32) sS[i * 52 + j] *= inv;
    }
    __syncthreads();

    for (int idx = tid; idx < NTOK * HDIM; idx += 256) {
        int i = idx >> 5, d = idx & 31;
        float o = 0.f;
#pragma unroll 7
        for (int j = 0; j < NTOK; j++) o += sS[i * 52 + j] * sv[j * 33 + d];
        g_ao[((size_t)(win * NTOK + i)) * CCH + nh * HDIM + d] =
            __float2bfloat16_rn(o);
    }
}

// ---------------------------------------------------------------------------
// K4: LN2 (bf16 out)
// ---------------------------------------------------------------------------
__global__ void __launch_bounds__(256) k_ln2(
    const float* __restrict__ g2, const float* __restrict__ b2)
{
    const int warp = threadIdx.x >> 5, lane = threadIdx.x & 31;
    const size_t tok = (size_t)blockIdx.x * 8 + warp;
    const float* p = g_x2 + tok * CCH;
    float v[12];
    float s = 0.f, s2 = 0.f;
#pragma unroll
    for (int i = 0; i < 12; i++) {
        v[i] = p[lane + i * 32];
        s += v[i]; s2 += v[i] * v[i];
    }
#pragma unroll
    for (int o = 16; o; o >>= 1) {
        s  += __shfl_xor_sync(0xffffffffu, s,  o);
        s2 += __shfl_xor_sync(0xffffffffu, s2, o);
    }
    float mu = s * (1.0f / CCH);
    float rs = rsqrtf(s2 * (1.0f / CCH) - mu * mu + 1e-5f);
    __nv_bfloat16* q = g_xn2 + tok * CCH;
#pragma unroll
    for (int i = 0; i < 12; i++) {
        int c = lane + i * 32;
        q[c] = __float2bfloat16_rn(
            (v[i] - mu) * rs * __ldg(&g2[c]) + __ldg(&b2[c]));
    }
}

// ---------------------------------------------------------------------------
// K5: NHWC -> NCHW
// ---------------------------------------------------------------------------
__global__ void __launch_bounds__(256) k_tr(float* __restrict__ out)
{
    __shared__ float t[32 * 57];
    const int bh = blockIdx.x;
    const int c0 = blockIdx.y * 32;
    const int b = bh / HH, h = bh % HH;
    const float* yp = g_y + (size_t)bh * WW2 * CCH + c0;

    for (int idx = threadIdx.x; idx < WW2 * 32; idx += 256) {
        int w = idx >> 5, cc = idx & 31;
        t[cc * 57 + w] = yp[(size_t)w * CCH + cc];
    }
    __syncthreads();
    float* op = out + (size_t)b * CCH * (HH * WW2) + (size_t)c0 * (HH * WW2) + h * WW2;
    for (int idx = threadIdx.x; idx < WW2 * 32; idx += 256) {
        int cc = idx / WW2, w = idx % WW2;
        op[(size_t)cc * (HH * WW2) + w] = t[cc * 57 + w];
    }
}

// ---------------------------------------------------------------------------
extern "C" void kernel_launch(void* const* d_in, const int* in_sizes, int n_in,
                              void* d_out, int out_size)
{
    const float* x       = (const float*)d_in[0];
    const float* norm1_g = (const float*)d_in[1];
    const float* norm1_b = (const float*)d_in[2];
    const float* qkv_w   = (const float*)d_in[3];
    const float* qkv_b   = (const float*)d_in[4];
    const float* proj_w  = (const float*)d_in[5];
    const float* proj_b  = (const float*)d_in[6];
    const float* norm2_g = (const float*)d_in[7];
    const float* norm2_b = (const float*)d_in[8];
    const float* fc1_w   = (const float*)d_in[9];
    const float* fc1_b   = (const float*)d_in[10];
    const float* fc2_w   = (const float*)d_in[11];
    const float* fc2_b   = (const float*)d_in[12];

    __nv_bfloat16 *p_xw, *p_ao, *p_xn2, *p_h1;
    __nv_bfloat16 *p_wqkv, *p_wproj, *p_wfc1, *p_wfc2;
    cudaGetSymbolAddress((void**)&p_xw,   g_xw);
    cudaGetSymbolAddress((void**)&p_ao,   g_ao);
    cudaGetSymbolAddress((void**)&p_xn2,  g_xn2);
    cudaGetSymbolAddress((void**)&p_h1,   g_h1);
    cudaGetSymbolAddress((void**)&p_wqkv, g_wt_qkv);
    cudaGetSymbolAddress((void**)&p_wproj,g_wt_proj);
    cudaGetSymbolAddress((void**)&p_wfc1, g_wt_fc1);
    cudaGetSymbolAddress((void**)&p_wfc2, g_wt_fc2);

    const int ln1_smem = 384 * 57 * sizeof(float);
    cudaFuncSetAttribute(k_ln1_window,
                         cudaFuncAttributeMaxDynamicSharedMemorySize, ln1_smem);

    // 0) weight prep: transpose + bf16
    k_wtprep<<<dim3(1152 / 32, 384 / 32), 256>>>(qkv_w, p_wqkv, 384, 1152);
    k_wtprep<<<dim3(384 / 32, 384 / 32), 256>>>(proj_w, p_wproj, 384, 384);
    k_wtprep<<<dim3(MLPD / 32, 384 / 32), 256>>>(fc1_w, p_wfc1, 384, MLPD);
    k_wtprep<<<dim3(384 / 32, MLPD / 32), 256>>>(fc2_w, p_wfc2, MLPD, 384);

    // 1) LN1 + transpose + shifted window partition
    k_ln1_window<<<16 * HH, 256, ln1_smem>>>(x, norm1_g, norm1_b);

    // 2) QKV GEMM: [50176,384] x [384,1152]
    k_gemm_bf16<0><<<dim3(1152 / 128, TOK / 128), 256>>>(
        p_xw, p_wqkv, qkv_b, 384, 1152, 12);

    // 3) windowed attention
    k_attn<<<NWIN * NHEAD, 256>>>();

    // 4) proj GEMM + window reverse + residual
    k_gemm_bf16<1><<<dim3(CCH / 128, TOK / 128), 256>>>(
        p_ao, p_wproj, proj_b, 384, CCH, 12);

    // 5) LN2
    k_ln2<<<TOK / 8, 256>>>(norm2_g, norm2_b);

    // 6) fc1 + GELU
    k_gemm_bf16<2><<<dim3(MLPD / 128, TOK / 128), 256>>>(
        p_xn2, p_wfc1, fc1_b, 384, MLPD, 12);

    // 7) fc2 + residual
    k_gemm_bf16<3><<<dim3(CCH / 128, TOK / 128), 256>>>(
        p_h1, p_wfc2, fc2_b, 1536, CCH, 48);

    // 8) NHWC -> NCHW
    k_tr<<<dim3(16 * HH, CCH / 32), 256>>>((float*)d_out);
}

// round 11
// speedup vs baseline: 2.0184x; 1.1821x over previous
#include <cuda_runtime.h>
#include <cuda_bf16.h>
#include <math.h>
#include <stdint.h>

// ---------------------------------------------------------------------------
// Swin block: B=16, C=384, H=W=56, NH=12, WS=7, SS=3, MLP=1536
// GEMMs: mma.sync m16n8k16 bf16 (fp32 accum), 128x128 CTA / 64x32 warp,
// k-chunk 32, reg double-buffer, ldmatrix fragment loads.
// Attention: fp32, register-blocked (4x4 QK^T, warp-4-row PV).
// fc2 epilogue writes NCHW directly; proj residual read from x NCHW.
// ---------------------------------------------------------------------------
#define TOK   50176
#define CCH   384
#define HH    56
#define WW2   56
#define NWIN  1024
#define NTOK  49
#define NHEAD 12
#define HDIM  32
#define MLPD  1536

// Scratch
__device__ __nv_bfloat16 g_xw [TOK * CCH];     // LN1 out (A of QKV)
__device__ float g_q  [TOK * CCH];
__device__ float g_k  [TOK * CCH];
__device__ float g_v  [TOK * CCH];
__device__ __nv_bfloat16 g_ao [TOK * CCH];     // attn out (A of proj)
__device__ float g_x2 [TOK * CCH];
__device__ __nv_bfloat16 g_xn2[TOK * CCH];     // LN2 out (A of fc1)
__device__ __nv_bfloat16 g_h1 [TOK * MLPD];    // gelu out (A of fc2)
// bf16 transposed weights [N][K]
__device__ __nv_bfloat16 g_wt_qkv [1152 * 384];
__device__ __nv_bfloat16 g_wt_proj[384 * 384];
__device__ __nv_bfloat16 g_wt_fc1 [MLPD * 384];
__device__ __nv_bfloat16 g_wt_fc2 [384 * MLPD];

__device__ __forceinline__ uint32_t smem_u32(const void* p) {
    uint32_t a;
    asm("{ .reg .u64 t; cvta.to.shared.u64 t, %1; cvt.u32.u64 %0, t; }"
        : "=r"(a) : "l"(p));
    return a;
}

// ---------------------------------------------------------------------------
// K0: weight prep: W[K][N] fp32 -> Wt[N][K] bf16
// ---------------------------------------------------------------------------
__global__ void __launch_bounds__(256) k_wtprep(const float* __restrict__ W,
                                                __nv_bfloat16* __restrict__ Wt,
                                                int K, int N)
{
    __shared__ float t[32][33];
    const int n0 = blockIdx.x * 32, k0 = blockIdx.y * 32;
    const int lx = threadIdx.x & 31, ly = threadIdx.x >> 5;
#pragma unroll
    for (int i = 0; i < 4; i++)
        t[ly + i * 8][lx] = W[(size_t)(k0 + ly + i * 8) * N + n0 + lx];
    __syncthreads();
#pragma unroll
    for (int i = 0; i < 4; i++)
        Wt[(size_t)(n0 + ly + i * 8) * K + k0 + lx] =
            __float2bfloat16_rn(t[lx][ly + i * 8]);
}

// ---------------------------------------------------------------------------
// bf16 mma GEMM: C = A[M,K] * Bt[N,K]^T, fp32 accum.
// CTA 128x128, 8 warps (2M x 4N), warp 64x32, k-chunk 32, reg double-buffer.
// MODE 0: QKV split  1: proj+winrev+residual(x NCHW)  2: fc1+GELU
// MODE 3: fc2+residual -> NCHW output directly
// ---------------------------------------------------------------------------
template <int MODE>
__global__ void __launch_bounds__(256, 2) k_gemm_bf16(
    const __nv_bfloat16* __restrict__ A, const __nv_bfloat16* __restrict__ Bt,
    const float* __restrict__ bias, float* __restrict__ aux,
    int K, int N, int NC)
{
    __shared__ uint32_t As[2][4][128][4];   // 16 KB
    __shared__ uint32_t Bs[2][4][128][4];   // 16 KB

    const int tid = threadIdx.x;
    const int wid = tid >> 5, lane = tid & 31;
    const int gid = lane >> 2, tig = lane & 3;
    const int wm = wid & 1, wn = wid >> 1;       // 2 x 4 warp grid
    const int m0 = blockIdx.y * 128, n0 = blockIdx.x * 128;

    const uint32_t sA = smem_u32(As), sB = smem_u32(Bs);
    const int rowA = wm * 64 + ((lane >> 3) & 1) * 8 + (lane & 7);
    const int kgoA = lane >> 4;
    const int rowB = wn * 32 + (lane & 7);
    const int kgoB = (lane >> 3) & 1;

    float acc[4][4][4];
#pragma unroll
    for (int a = 0; a < 4; a++)
#pragma unroll
        for (int b = 0; b < 4; b++)
#pragma unroll
            for (int c = 0; c < 4; c++) acc[a][b][c] = 0.f;

    const int st_row = tid >> 2;
    const int st_kg = tid & 3;

    uint4 la[2], lb[2];

    auto ldg_chunk = [&](int c) {
#pragma unroll
        for (int t = 0; t < 2; t++) {
            int row = t * 64 + st_row;
            la[t] = *reinterpret_cast<const uint4*>(
                A + (size_t)(m0 + row) * K + c * 32 + st_kg * 8);
            lb[t] = *reinterpret_cast<const uint4*>(
                Bt + (size_t)(n0 + row) * K + c * 32 + st_kg * 8);
        }
    };
    auto sts_chunk = [&](int s) {
#pragma unroll
        for (int t = 0; t < 2; t++) {
            int row = t * 64 + st_row;
            *reinterpret_cast<uint4*>(&As[s][st_kg][row][0]) = la[t];
            *reinterpret_cast<uint4*>(&Bs[s][st_kg][row][0]) = lb[t];
        }
    };

    auto compute = [&](int s) {
#pragma unroll
        for (int ks = 0; ks < 2; ks++) {
            uint32_t af[4][4], bf[4][2];
#pragma unroll
            for (int mi = 0; mi < 4; mi++) {
                uint32_t addr = sA +
                    (uint32_t)(((s * 4 + ks * 2 + kgoA) * 128 +
                                rowA + mi * 16) * 16);
                asm volatile(
                    "ldmatrix.sync.aligned.m8n8.x4.shared.b16 "
                    "{%0,%1,%2,%3}, [%4];"
                    : "=r"(af[mi][0]), "=r"(af[mi][1]),
                      "=r"(af[mi][2]), "=r"(af[mi][3])
                    : "r"(addr));
            }
#pragma unroll
            for (int ni = 0; ni < 4; ni++) {
                uint32_t addr = sB +
                    (uint32_t)(((s * 4 + ks * 2 + kgoB) * 128 +
                                rowB + ni * 8) * 16);
                asm volatile(
                    "ldmatrix.sync.aligned.m8n8.x2.shared.b16 "
                    "{%0,%1}, [%2];"
                    : "=r"(bf[ni][0]), "=r"(bf[ni][1])
                    : "r"(addr));
            }
#pragma unroll
            for (int mi = 0; mi < 4; mi++)
#pragma unroll
                for (int ni = 0; ni < 4; ni++)
                    asm volatile(
                        "mma.sync.aligned.m16n8k16.row.col.f32.bf16.bf16.f32 "
                        "{%0,%1,%2,%3},{%4,%5,%6,%7},{%8,%9},{%0,%1,%2,%3};"
                        : "+f"(acc[mi][ni][0]), "+f"(acc[mi][ni][1]),
                          "+f"(acc[mi][ni][2]), "+f"(acc[mi][ni][3])
                        : "r"(af[mi][0]), "r"(af[mi][1]),
                          "r"(af[mi][2]), "r"(af[mi][3]),
                          "r"(bf[ni][0]), "r"(bf[ni][1]));
        }
    };

    int s = 0;
    ldg_chunk(0);
    sts_chunk(0);
    __syncthreads();
    for (int c = 0; c < NC; c++) {
        if (c + 1 < NC) ldg_chunk(c + 1);
        compute(s);
        if (c + 1 < NC) sts_chunk(s ^ 1);
        __syncthreads();
        s ^= 1;
    }

    // ---------------- epilogue: fused scatter from accumulators -------------
    const float qscale = 0.17677669529663687f;

    auto store_pair = [&](int m, int n, float vx, float vy) {
        vx += __ldg(&bias[n]);
        vy += __ldg(&bias[n + 1]);
        if (MODE == 0) {
            int tq = n / CCH;
            int rem = n - tq * CCH;
            int head = rem >> 5, hd = rem & 31;
            int win = m / NTOK, tokn = m - win * NTOK;
            float scl = (tq == 0) ? qscale : 1.0f;
            float* dst = (tq == 0) ? g_q : (tq == 1) ? g_k : g_v;
            size_t o = (((size_t)(win * NHEAD + head)) * NTOK + tokn) * HDIM + hd;
            *reinterpret_cast<float2*>(dst + o) = make_float2(vx * scl, vy * scl);
        } else if (MODE == 1) {
            int win = m / NTOK, tokn = m - win * NTOK;
            int b = win >> 6, widx = win & 63;
            int h = (widx >> 3) * 7 + tokn / 7 + 3; if (h >= HH)  h -= HH;
            int w = (widx & 7) * 7 + tokn % 7 + 3;  if (w >= WW2) w -= WW2;
            int hw = h * WW2 + w;
            size_t tk = (size_t)b * (HH * WW2) + hw;
            // residual straight from x (NCHW)
            float rx = __ldg(aux + ((size_t)b * CCH + n) * (HH * WW2) + hw);
            float ry = __ldg(aux + ((size_t)b * CCH + n + 1) * (HH * WW2) + hw);
            *reinterpret_cast<float2*>(g_x2 + tk * CCH + n) =
                make_float2(vx + rx, vy + ry);
        } else if (MODE == 2) {
            vx = 0.5f * vx * (1.0f + erff(vx * 0.70710678118654752f));
            vy = 0.5f * vy * (1.0f + erff(vy * 0.70710678118654752f));
            *reinterpret_cast<__nv_bfloat162*>(g_h1 + (size_t)m * MLPD + n) =
                __floats2bfloat162_rn(vx, vy);
        } else {
            float2 r = *reinterpret_cast<const float2*>(g_x2 + (size_t)m * CCH + n);
            // direct NCHW output
            int b = m / (HH * WW2), hw = m - b * (HH * WW2);
            aux[((size_t)b * CCH + n) * (HH * WW2) + hw] = vx + r.x;
            aux[((size_t)b * CCH + n + 1) * (HH * WW2) + hw] = vy + r.y;
        }
    };

#pragma unroll
    for (int mi = 0; mi < 4; mi++) {
#pragma unroll
        for (int ni = 0; ni < 4; ni++) {
            int m = m0 + wm * 64 + mi * 16 + gid;
            int n = n0 + wn * 32 + ni * 8 + tig * 2;
            store_pair(m,     n, acc[mi][ni][0], acc[mi][ni][1]);
            store_pair(m + 8, n, acc[mi][ni][2], acc[mi][ni][3]);
        }
    }
}

// ---------------------------------------------------------------------------
// K1: LN1 + NCHW->NHWC + shifted-window partition (bf16 out only)
// ---------------------------------------------------------------------------
__global__ void __launch_bounds__(256) k_ln1_window(
    const float* __restrict__ x, const float* __restrict__ g1,
    const float* __restrict__ b1)
{
    extern __shared__ float sm[];
    __shared__ float smu[56], srs[56];
    const int bh = blockIdx.x;
    const int b = bh / HH, h = bh % HH;
    const int tid = threadIdx.x;
    const float* xp = x + (size_t)b * CCH * (HH * WW2) + (size_t)h * WW2;

    for (int idx = tid; idx < CCH * WW2; idx += 256) {
        int c = idx / WW2, w = idx % WW2;
        sm[c * 57 + w] = xp[(size_t)c * (HH * WW2) + w];
    }
    __syncthreads();
    if (tid < WW2) {
        float s = 0.f, s2 = 0.f;
        for (int c = 0; c < CCH; c++) {
            float t = sm[c * 57 + tid];
            s += t; s2 += t * t;
        }
        float mu = s * (1.0f / CCH);
        smu[tid] = mu;
        srs[tid] = rsqrtf(s2 * (1.0f / CCH) - mu * mu + 1e-5f);
    }
    __syncthreads();

    int hp = h - 3; if (hp < 0) hp += HH;
    const int wh = hp / 7, rr = hp % 7;
    for (int idx = tid; idx < WW2 * CCH; idx += 256) {
        int w = idx / CCH, c = idx % CCH;
        float val = sm[c * 57 + w];
        float nv = (val - smu[w]) * srs[w] * __ldg(&g1[c]) + __ldg(&b1[c]);
        int wp = w - 3; if (wp < 0) wp += WW2;
        int win = (b * 8 + wh) * 8 + wp / 7;
        g_xw[((size_t)win * NTOK + rr * 7 + wp % 7) * CCH + c] =
            __float2bfloat16_rn(nv);
    }
}

// ---------------------------------------------------------------------------
// K3: windowed attention, register-blocked.
// QK^T: thread = 4x4 tile (13x13 units over padded 52x52 S).
// PV: warp = 4 rows x 32 dims, 2 passes.
// ---------------------------------------------------------------------------
__global__ void __launch_bounds__(256) k_attn()
{
    __shared__ float sq[52 * 33], sk[52 * 33], sv[NTOK * 33];
    __shared__ float sS[52 * 52];
    __shared__ int   sid[52];

    const int win = blockIdx.x / NHEAD;
    const int nh  = blockIdx.x % NHEAD;
    const int tid = threadIdx.x;
    const size_t base = ((size_t)(win * NHEAD + nh)) * NTOK * HDIM;

    for (int idx = tid; idx < NTOK * HDIM; idx += 256) {
        int r = idx >> 5, c = idx & 31;
        sq[r * 33 + c] = g_q[base + idx];
        sk[r * 33 + c] = g_k[base + idx];
        sv[r * 33 + c] = g_v[base + idx];
    }
    // zero pad rows 49..51 of sq/sk
    for (int idx = tid; idx < 3 * 33; idx += 256) {
        sq[NTOK * 33 + idx] = 0.f;
        sk[NTOK * 33 + idx] = 0.f;
    }
    if (tid < 52) {
        int v = 0;
        if (tid < NTOK) {
            int widx = win & 63;
            int hp = (widx >> 3) * 7 + tid / 7;
            int wp = (widx & 7) * 7 + tid % 7;
            int hr = (hp < 49) ? 0 : (hp < 53 ? 1 : 2);
            int wr = (wp < 49) ? 0 : (wp < 53 ? 1 : 2);
            v = hr * 3 + wr;
        }
        sid[tid] = v;
    }
    __syncthreads();

    // ---- QK^T, 4x4 register tile per thread ----
    if (tid < 169) {
        const int iq = (tid / 13) * 4, jq = (tid % 13) * 4;
        float acc[4][4];
#pragma unroll
        for (int r = 0; r < 4; r++)
#pragma unroll
            for (int c = 0; c < 4; c++) acc[r][c] = 0.f;
#pragma unroll
        for (int l = 0; l < HDIM; l++) {
            float qa[4], kb[4];
#pragma unroll
            for (int r = 0; r < 4; r++) qa[r] = sq[(iq + r) * 33 + l];
#pragma unroll
            for (int c = 0; c < 4; c++) kb[c] = sk[(jq + c) * 33 + l];
#pragma unroll
            for (int r = 0; r < 4; r++)
#pragma unroll
                for (int c = 0; c < 4; c++) acc[r][c] += qa[r] * kb[c];
        }
#pragma unroll
        for (int r = 0; r < 4; r++)
#pragma unroll
            for (int c = 0; c < 4; c++) {
                int i = iq + r, j = jq + c;
                float sc = acc[r][c];
                if (sid[i] != sid[j]) sc -= 100.0f;
                sS[i * 52 + j] = sc;
            }
    }
    __syncthreads();

    // ---- softmax (rows 0..48) ----
    const int warp = tid >> 5, lane = tid & 31;
    for (int i = warp; i < NTOK; i += 8) {
        float mx = -1e30f;
        for (int j = lane; j < NTOK; j += 32) mx = fmaxf(mx, sS[i * 52 + j]);
#pragma unroll
        for (int o = 16; o; o >>= 1) mx = fmaxf(mx, __shfl_xor_sync(0xffffffffu, mx, o));
        float sum = 0.f;
        for (int j = lane; j < NTOK; j += 32) {
            float e = __expf(sS[i * 52 + j] - mx);
            sS[i * 52 + j] = e;
            sum += e;
        }
#pragma unroll
        for (int o = 16; o; o >>= 1) sum += __shfl_xor_sync(0xffffffffu, sum, o);
        float inv = 1.0f / sum;
        for (int j = lane; j < NTOK; j += 32) sS[i * 52 + j] *= inv;
    }
    __syncthreads();

    // ---- PV: warp handles 4 rows x 32 dims, 2 passes ----
#pragma unroll
    for (int pass = 0; pass < 2; pass++) {
        int r0 = pass * 32 + warp * 4;
        if (r0 < NTOK) {
            float o[4] = {0.f, 0.f, 0.f, 0.f};
            for (int j = 0; j < NTOK; j++) {
                float v = sv[j * 33 + lane];
#pragma unroll
                for (int r = 0; r < 4; r++)
                    o[r] += sS[(r0 + r) * 52 + j] * v;
            }
#pragma unroll
            for (int r = 0; r < 4; r++) {
                int i = r0 + r;
                if (i < NTOK)
                    g_ao[((size_t)(win * NTOK + i)) * CCH + nh * HDIM + lane] =
                        __float2bfloat16_rn(o[r]);
            }
        }
    }
}

// ---------------------------------------------------------------------------
// K4: LN2 (bf16 out)
// ---------------------------------------------------------------------------
__global__ void __launch_bounds__(256) k_ln2(
    const float* __restrict__ g2, const float* __restrict__ b2)
{
    const int warp = threadIdx.x >> 5, lane = threadIdx.x & 31;
    const size_t tok = (size_t)blockIdx.x * 8 + warp;
    const float* p = g_x2 + tok * CCH;
    float v[12];
    float s = 0.f, s2 = 0.f;
#pragma unroll
    for (int i = 0; i < 12; i++) {
        v[i] = p[lane + i * 32];
        s += v[i]; s2 += v[i] * v[i];
    }
#pragma unroll
    for (int o = 16; o; o >>= 1) {
        s  += __shfl_xor_sync(0xffffffffu, s,  o);
        s2 += __shfl_xor_sync(0xffffffffu, s2, o);
    }
    float mu = s * (1.0f / CCH);
    float rs = rsqrtf(s2 * (1.0f / CCH) - mu * mu + 1e-5f);
    __nv_bfloat16* q = g_xn2 + tok * CCH;
#pragma unroll
    for (int i = 0; i < 12; i++) {
        int c = lane + i * 32;
        q[c] = __float2bfloat16_rn(
            (v[i] - mu) * rs * __ldg(&g2[c]) + __ldg(&b2[c]));
    }
}

// ---------------------------------------------------------------------------
extern "C" void kernel_launch(void* const* d_in, const int* in_sizes, int n_in,
                              void* d_out, int out_size)
{
    const float* x       = (const float*)d_in[0];
    const float* norm1_g = (const float*)d_in[1];
    const float* norm1_b = (const float*)d_in[2];
    const float* qkv_w   = (const float*)d_in[3];
    const float* qkv_b   = (const float*)d_in[4];
    const float* proj_w  = (const float*)d_in[5];
    const float* proj_b  = (const float*)d_in[6];
    const float* norm2_g = (const float*)d_in[7];
    const float* norm2_b = (const float*)d_in[8];
    const float* fc1_w   = (const float*)d_in[9];
    const float* fc1_b   = (const float*)d_in[10];
    const float* fc2_w   = (const float*)d_in[11];
    const float* fc2_b   = (const float*)d_in[12];

    __nv_bfloat16 *p_xw, *p_ao, *p_xn2, *p_h1;
    __nv_bfloat16 *p_wqkv, *p_wproj, *p_wfc1, *p_wfc2;
    cudaGetSymbolAddress((void**)&p_xw,   g_xw);
    cudaGetSymbolAddress((void**)&p_ao,   g_ao);
    cudaGetSymbolAddress((void**)&p_xn2,  g_xn2);
    cudaGetSymbolAddress((void**)&p_h1,   g_h1);
    cudaGetSymbolAddress((void**)&p_wqkv, g_wt_qkv);
    cudaGetSymbolAddress((void**)&p_wproj,g_wt_proj);
    cudaGetSymbolAddress((void**)&p_wfc1, g_wt_fc1);
    cudaGetSymbolAddress((void**)&p_wfc2, g_wt_fc2);

    const int ln1_smem = 384 * 57 * sizeof(float);
    cudaFuncSetAttribute(k_ln1_window,
                         cudaFuncAttributeMaxDynamicSharedMemorySize, ln1_smem);

    // 0) weight prep: transpose + bf16
    k_wtprep<<<dim3(1152 / 32, 384 / 32), 256>>>(qkv_w, p_wqkv, 384, 1152);
    k_wtprep<<<dim3(384 / 32, 384 / 32), 256>>>(proj_w, p_wproj, 384, 384);
    k_wtprep<<<dim3(MLPD / 32, 384 / 32), 256>>>(fc1_w, p_wfc1, 384, MLPD);
    k_wtprep<<<dim3(384 / 32, MLPD / 32), 256>>>(fc2_w, p_wfc2, MLPD, 384);

    // 1) LN1 + transpose + shifted window partition
    k_ln1_window<<<16 * HH, 256, ln1_smem>>>(x, norm1_g, norm1_b);

    // 2) QKV GEMM: [50176,384] x [384,1152]
    k_gemm_bf16<0><<<dim3(1152 / 128, TOK / 128), 256>>>(
        p_xw, p_wqkv, qkv_b, nullptr, 384, 1152, 12);

    // 3) windowed attention
    k_attn<<<NWIN * NHEAD, 256>>>();

    // 4) proj GEMM + window reverse + residual from x (NCHW)
    k_gemm_bf16<1><<<dim3(CCH / 128, TOK / 128), 256>>>(
        p_ao, p_wproj, proj_b, (float*)x, 384, CCH, 12);

    // 5) LN2
    k_ln2<<<TOK / 8, 256>>>(norm2_g, norm2_b);

    // 6) fc1 + GELU
    k_gemm_bf16<2><<<dim3(MLPD / 128, TOK / 128), 256>>>(
        p_xn2, p_wfc1, fc1_b, nullptr, 384, MLPD, 12);

    // 7) fc2 + residual -> NCHW output directly
    k_gemm_bf16<3><<<dim3(CCH / 128, TOK / 128), 256>>>(
        p_h1, p_wfc2, fc2_b, (float*)d_out, 1536, CCH, 48);
}